// round 17
// baseline (speedup 1.0000x reference)
#include <cuda_runtime.h>

// DILATE loss — band-wavefront soft-DTW, one CTA per batch (grid 256).
// R17 = R16 with tighter wavefront: 8-step phases, 40-column warp skew
// (margin = skew-31 = 9 >= phase+1). Span per pass: 40*10+368 = 768 steps
// (was 847). Wall scales with span (confirmed R16: x0.841 predicted = measured).
// Forward stores softmin gradient weights (wd,wu) float2; backward is the
// MUFU-free linear recurrence E = Pu + Pl + Pd. Base-2 math. PF=8 ring.

#define NB    256
#define NN    336
#define NV    7
#define ND    673
#define DS    352
#define TPB   352
#define NW    11
#define W2    512
#define PADJ  64
#define PSTR  12
#define NPTS  (NN + 2*PADJ)
#define LOG2E 1.4426950408889634f
#define LN2   0.6931471805599453f
#define BIG2  1.442695e8f
#define PF    8
#define NPH   96            // phases per pass (span 768 / 8)
#define FULLM 0xffffffffu

// weights, diagonal-major; 32 diag front pad + 64 back pad
__device__ float2   g_W[((size_t)NB * ND + 96) * DS];
__device__ double   g_shape_acc;
__device__ double   g_temp_acc;
__device__ unsigned g_done;

static __device__ __forceinline__ float ex2f(float x){float r;asm("ex2.approx.f32 %0,%1;":"=f"(r):"f"(x));return r;}
static __device__ __forceinline__ float lg2f(float x){float r;asm("lg2.approx.f32 %0,%1;":"=f"(r):"f"(x));return r;}
static __device__ __forceinline__ float rcpf(float x){float r;asm("rcp.approx.f32 %0,%1;":"=f"(r):"f"(x));return r;}

extern __shared__ float smem[];

__global__ __launch_bounds__(TPB, 2)
void dilate_kernel(const float* __restrict__ outputs,
                   const float* __restrict__ targets,
                   float* __restrict__ out) {
    const int b   = blockIdx.x;
    const int tid = threadIdx.x;
    const int w   = tid >> 5;
    const int l   = tid & 31;
    const int i   = 32 * w + l + 1;
    const bool row_ok = (i <= NN);

    float* opack = smem;                     // [NPTS][PSTR]: 0-6 dims, 7 = log2e*||o||^2
    float* bnd1  = opack + NPTS * PSTR;      // fwd: R boundary; bwd: Pu   [NW][W2]
    float* bnd2  = bnd1 + NW * W2;           // bwd: Pd
    __shared__ float warpsum[NW];
    __shared__ float shape_s;

    const float* ob = outputs + (size_t)b * NN * NV;
    const float* tb = targets + (size_t)b * NN * NV;

    for (int k = tid; k < NPTS * PSTR; k += TPB) opack[k] = 0.f;
    __syncthreads();
    for (int k = tid; k < NN * NV; k += TPB) {
        int j = k / NV, v = k - j * NV;
        opack[(j + PADJ) * PSTR + v] = ob[k];
    }
    __syncthreads();
    for (int j = tid; j < NN; j += TPB) {
        float s = 0.f;
#pragma unroll
        for (int v = 0; v < NV; v++) { float x = opack[(j + PADJ) * PSTR + v]; s = fmaf(x, x, s); }
        opack[(j + PADJ) * PSTR + 7] = s * LOG2E;
    }
    float tL[NV], tn2 = 0.f;
    if (row_ok) {
        float tnr = 0.f;
#pragma unroll
        for (int v = 0; v < NV; v++) {
            float tv = tb[(i - 1) * NV + v];
            tnr = fmaf(tv, tv, tnr);
            tL[v] = 2.f * LOG2E * tv;
        }
        tn2 = tnr * LOG2E;
    } else {
#pragma unroll
        for (int v = 0; v < NV; v++) tL[v] = 0.f;
    }
    // forward boundary prefill: BIG2 everywhere except R[0][0]=0 (race-free fill)
    for (int k = tid; k < NW * W2; k += TPB) bnd1[k] = (k == PADJ) ? 0.f : BIG2;
    if (tid == 0) shape_s = 0.f;
    __syncthreads();

    float2* gWb = g_W + 32 * (size_t)DS + (size_t)b * ND * DS;
    const bool nn_lane = (i == NN);

    // ================= forward =================
    {
        float Rprev = BIG2, upc = BIG2, upp = BIG2, prevB = BIG2;
        const int off = 40 * w;
        const int pstart = 5 * w, pend = 5 * w + 45;
        const float* bArow = bnd1 + w * W2 + PADJ;
        float* bAnext = bnd1 + (w + 1) * W2 + PADJ;
        for (int p = 0; p < NPH; p++) {
            if (p >= pstart && p <= pend) {
                int s0 = p << 3;
                int j = s0 - off - l + 1;
                if (p == pstart && l == 0) prevB = bArow[0];
                float2* gptr = gWb + (size_t)(s0 - 8 * w + 2) * DS + i;
                const float* oj = opack + (j - 1 + PADJ) * PSTR;
#pragma unroll
                for (int k = 0; k < 8; k++) {
                    bool act = row_ok && ((unsigned)(j - 1) < (unsigned)NN);
                    const float4 a = *(const float4*)(oj);
                    const float4 c = *(const float4*)(oj + 4);
                    float acc0 = tn2 + c.w;
                    acc0 = fmaf(-tL[0], a.x, acc0);
                    acc0 = fmaf(-tL[1], a.y, acc0);
                    acc0 = fmaf(-tL[2], a.z, acc0);
                    acc0 = fmaf(-tL[3], a.w, acc0);
                    acc0 = fmaf(-tL[4], c.x, acc0);
                    acc0 = fmaf(-tL[5], c.y, acc0);
                    acc0 = fmaf(-tL[6], c.z, acc0);
                    float D2 = fmaxf(acc0, 0.f);
                    float ru = upc, rd = upp, curB = 0.f;
                    if (l == 0) { curB = bArow[j]; ru = curB; rd = prevB; }
                    float rl = Rprev;
                    float m  = fminf(fminf(rd, ru), rl);
                    float ed = ex2f(m - rd);
                    float eu = ex2f(m - ru);
                    float el = ex2f(m - rl);
                    float z  = ed + eu + el;
                    float Rn = D2 + m - lg2f(z);
                    float rz = rcpf(z);
                    Rn = act ? Rn : BIG2;
                    if (act) {
                        *gptr = make_float2(ed * rz, eu * rz);
                        if (l == 31 && w < NW - 1) bAnext[j] = Rn;
                        if (nn_lane && j == NN) shape_s = Rn * LN2;
                    }
                    float sh = __shfl_up_sync(FULLM, Rn, 1);
                    upp = upc; upc = sh;
                    if (l == 0) prevB = curB;
                    Rprev = Rn;
                    j++; gptr += DS; oj += PSTR;
                }
            }
            __syncthreads();
        }
    }

    // re-init boundaries for backward: products = 0
    for (int k = tid; k < NW * W2; k += TPB) { bnd1[k] = 0.f; bnd2[k] = 0.f; }
    __syncthreads();

    // ================= backward (pure linear recurrence) =================
    float tacc = 0.f;
    {
        float Plp  = 0.f;
        float PuD1 = 0.f, PdD1 = 0.f;
        float PdD2 = 0.f;
        float puC = 0.f, pdC = 0.f;          // lane31 boundary prefetch regs
        float2 ring[PF];
        const int off = 40 * (10 - w);
        const int pstart = 5 * (10 - w), pend = 5 * (10 - w) + 45;
        const float* b1row = bnd1 + w * W2 + PADJ;
        const float* b2row = bnd2 + w * W2 + PADJ;
        float* b1prev = bnd1 + (w - 1) * W2 + PADJ;
        float* b2prev = bnd2 + (w - 1) * W2 + PADJ;
        for (int p = 0; p < NPH; p++) {
            if (p >= pstart && p <= pend) {
                int s0 = p << 3;
                if (p == pstart) {
                    const float2* pr = gWb + (size_t)(768 - 8 * w - s0) * DS + i;
#pragma unroll
                    for (int q = 0; q < PF; q++) { ring[q] = *pr; pr -= DS; }
                    if (l == 31) {           // first col for lane31: j0 = 336
                        puC = b1row[336];
                        pdC = b2row[336];
                    }
                }
                int j = 367 + off - s0 - l;
                float df = (float)(i - j);
                const float2* ppf = gWb + (size_t)(768 - 8 * w - s0 - PF) * DS + i;
#pragma unroll
                for (int kk = 0; kk < PF; kk++) {
                    bool act = row_ok && ((unsigned)(j - 1) < (unsigned)NN);
                    float2 Wv = ring[kk];
                    ring[kk] = *ppf; ppf -= DS;
                    if (l == 31) {
                        PuD1 = puC; PdD1 = pdC;
                        puC = b1row[j - 1];  // prefetch next step's column
                        pdC = b2row[j - 1];
                    }
                    float En = PuD1 + Plp + PdD2;
                    if (nn_lane && j == NN) En = 1.f;
                    En = act ? En : 0.f;
                    float wl = 1.f - Wv.x - Wv.y;
                    float Pd = En * Wv.x;
                    float Pu = En * Wv.y;
                    float Pl = En * wl;
                    tacc = fmaf(En, df * df, tacc);
                    if (act && l == 0 && w > 0) { b1prev[j] = Pu; b2prev[j] = Pd; }
                    float sPu = __shfl_down_sync(FULLM, Pu, 1);
                    float sPd = __shfl_down_sync(FULLM, Pd, 1);
                    PdD2 = PdD1;
                    if (l != 31) { PuD1 = sPu; PdD1 = sPd; }
                    Plp = Pl;
                    j--; df += 1.f;
                }
            }
            __syncthreads();
        }
    }

    // ------- reduce temporal accumulator, finalize in last CTA -------
#pragma unroll
    for (int o2 = 16; o2; o2 >>= 1) tacc += __shfl_down_sync(FULLM, tacc, o2);
    if (l == 0) warpsum[w] = tacc;
    __syncthreads();
    if (tid == 0) {
        float sum = 0.f;
#pragma unroll
        for (int q = 0; q < NW; q++) sum += warpsum[q];
        atomicAdd(&g_temp_acc, (double)sum);
        atomicAdd(&g_shape_acc, (double)shape_s);
        __threadfence();
        unsigned old = atomicAdd(&g_done, 1u);
        if (old == NB - 1) {
            __threadfence();
            double shape    = g_shape_acc / (double)NB;
            double temporal = g_temp_acc / ((double)NN * NN * NB * NB);
            out[0] = (float)(0.5 * shape + 0.5 * temporal);
            g_shape_acc = 0.0;
            g_temp_acc  = 0.0;
            __threadfence();
            g_done = 0u;
        }
    }
}

extern "C" void kernel_launch(void* const* d_in, const int* in_sizes, int n_in,
                              void* d_out, int out_size) {
    const float* outputs = (const float*)d_in[0];
    const float* targets = (const float*)d_in[1];
    static int smem_set = 0;
    int smem_bytes = (NPTS * PSTR + 2 * NW * W2) * sizeof(float);
    if (!smem_set) {
        cudaFuncSetAttribute(dilate_kernel, cudaFuncAttributeMaxDynamicSharedMemorySize,
                             smem_bytes);
        smem_set = 1;
    }
    dilate_kernel<<<NB, TPB, smem_bytes>>>(outputs, targets, (float*)d_out);
}